// round 14
// baseline (speedup 1.0000x reference)
#include <cuda_runtime.h>
#include <cstdint>

#define NN 50000
#define NPAD 50048          // padded row count (782 * 64)
#define EMAX 500000
#define HID 160
#define LD 164              // row stride of intermediates: 164 % 32 == 4 -> conflict-free frags

#define WP2_LD 164          // paired hid-W row stride in uint2 units
#define HDSZ32 (80 * WP2_LD * 2)   // uint32 words per hid W (26240)

// ---------------- scratch (static device globals; no allocation) ----------------
__device__ float g_feat[NPAD * LD];
__device__ float g_h1[NPAD * LD];
__device__ float g_mean[NPAD * LD];
__device__ float g_h2[NPAD * LD];
__device__ int g_deg[NN];
__device__ int g_offs[NN + 1];
__device__ int g_cursor[NN];
__device__ int g_csr[EMAX];
__device__ int g_is64;
// weights: 3x proj padded [768][40] + 4x hid paired [80][164] uint2
__device__ uint32_t g_wtf[3 * 768 * 40 + 4 * HDSZ32];

__device__ __forceinline__ float lrelu(float x) { return x > 0.f ? x : 0.01f * x; }

__device__ __forceinline__ uint32_t f2tf32(float x) {
    uint32_t u;
    asm("cvt.rna.tf32.f32 %0, %1;" : "=r"(u) : "f"(x));
    return u;
}
__device__ __forceinline__ float rtf(float x) { return __uint_as_float(f2tf32(x)); }

__device__ __forceinline__ uint32_t smem_u32(const void* p) {
    return (uint32_t)__cvta_generic_to_shared(p);
}

// ---------------- mbarrier + bulk-copy primitives ----------------
#define MBAR_INIT(addr, cnt) \
    asm volatile("mbarrier.init.shared.b64 [%0], %1;" :: "r"(addr), "r"(cnt) : "memory")
#define MBAR_EXPECT(addr, bytes) \
    asm volatile("mbarrier.arrive.expect_tx.shared.b64 _, [%0], %1;" :: "r"(addr), "r"(bytes) : "memory")
#define MBAR_WAITP(addr, ph) do { \
    asm volatile( \
        "{\n\t.reg .pred P;\n" \
        "WAITL_%=:\n\t" \
        "mbarrier.try_wait.parity.acquire.cta.shared::cta.b64 P, [%0], %1, 0x989680;\n\t" \
        "@P bra.uni WAITD_%=;\n\t" \
        "bra.uni WAITL_%=;\n" \
        "WAITD_%=:\n\t}" \
        :: "r"(addr), "r"((uint32_t)(ph)) : "memory"); } while (0)

__device__ __forceinline__ void bulkcp(uint32_t dst_smem, const void* src,
                                       uint32_t bytes, uint32_t mbar) {
    asm volatile(
        "cp.async.bulk.shared::cluster.global.mbarrier::complete_tx::bytes "
        "[%0], [%1], %2, [%3];"
        :: "r"(dst_smem), "l"(src), "r"(bytes), "r"(mbar) : "memory");
}

// ---------------- weight preconversion ----------------
struct WC {
    const float* src[7];
    int doff[7], cum[8];
};

__global__ void wconv_kernel(WC a) {
    int i = blockIdx.x * 256 + threadIdx.x;
    #pragma unroll
    for (int s = 0; s < 7; s++) {
        if (i >= a.cum[s] && i < a.cum[s + 1]) {
            int j = i - a.cum[s];
            if (s < 3) {
                int row = j / 32, col = j % 32;
                g_wtf[a.doff[s] + row * 40 + col] = f2tf32(a.src[s][j]);
            } else {
                int row = j / 160, col = j % 160;
                int kblk = row >> 3, tg = row & 3, half = (row >> 2) & 1;
                int idx32 = a.doff[s] + ((kblk * 4 + tg) * WP2_LD + col) * 2 + half;
                g_wtf[idx32] = f2tf32(a.src[s][j]);
            }
        }
    }
}

// Edge index may be int64 (reference) or int32 (JAX canonicalization).
__device__ __forceinline__ int edge_val(const void* ei, int idx) {
    if (g_is64) return (int)((const long long*)ei)[idx];
    return ((const int*)ei)[idx];
}

__global__ void detect_kernel(const void* ei, int E) {
    __shared__ int any_hi;
    int t = threadIdx.x;
    if (t == 0) any_hi = 0;
    __syncthreads();
    const unsigned long long* p = (const unsigned long long*)ei;
    int n = E < 1024 ? E : 1024;
    unsigned long long acc = 0;
    for (int i = t; i < n; i += 256) acc |= p[i];
    if (acc > 0xFFFFFFFFull) atomicOr(&any_hi, 1);
    __syncthreads();
    if (t == 0) g_is64 = any_hi ? 0 : 1;
}

// ============ shared GEMM tile body (paired-k W, LDS.64 b-frags) ============
#define FW_W_BYTES (HDSZ32 * 4)             // 104960
#define FW_TILE_BYTES (64 * LD * 4)         // 41984
#define FW_SMEM (128 + FW_W_BYTES + 2 * FW_TILE_BYTES)   // 189056
#define FWO_SMEM (FW_SMEM + 2 * 64 * 17 * 4)             // +8704 = 197760

template <bool LEAKY, bool ROUND>
__device__ __forceinline__ void fw_tile_body(
    const uint2* Wsp, const float (*As)[64][LD], int buf,
    const float* bias, float* C, int ldC, int M, int tileRow,
    int mw, int nw, int g, int tg)
{
    const int ncol0 = nw * 40;
    const int wb = tg * WP2_LD + ncol0 + g;
    const int r = mw * 16 + g;

    float acc[5][4] = {};
    #pragma unroll
    for (int kblk = 0; kblk < 20; kblk++) {
        const int kk = kblk * 8;
        uint32_t a0 = __float_as_uint(As[buf][r][kk + tg]);
        uint32_t a1 = __float_as_uint(As[buf][r + 8][kk + tg]);
        uint32_t a2 = __float_as_uint(As[buf][r][kk + tg + 4]);
        uint32_t a3 = __float_as_uint(As[buf][r + 8][kk + tg + 4]);
        const uint2* wrow = Wsp + kblk * (4 * WP2_LD) + wb;
        #pragma unroll
        for (int nt = 0; nt < 5; nt++) {
            uint2 bp = wrow[nt * 8];
            float* cc = acc[nt];
            asm volatile(
                "mma.sync.aligned.m16n8k8.row.col.f32.tf32.tf32.f32 "
                "{%0,%1,%2,%3}, {%4,%5,%6,%7}, {%8,%9}, {%0,%1,%2,%3};"
                : "+f"(cc[0]), "+f"(cc[1]), "+f"(cc[2]), "+f"(cc[3])
                : "r"(a0), "r"(a1), "r"(a2), "r"(a3), "r"(bp.x), "r"(bp.y));
        }
    }
    __syncthreads();   // all reads of buf done (caller may refill after)

    #pragma unroll
    for (int nt = 0; nt < 5; nt++) {
        int lc = ncol0 + nt * 8 + 2 * tg;
        float b0 = bias ? bias[lc] : 0.f;
        float b1 = bias ? bias[lc + 1] : 0.f;
        float* cc = acc[nt];
        int r0 = tileRow + mw * 16 + g;
        int r1 = r0 + 8;
        float v00 = cc[0] + b0, v01 = cc[1] + b1;
        float v10 = cc[2] + b0, v11 = cc[3] + b1;
        if (LEAKY) {
            v00 = lrelu(v00); v01 = lrelu(v01);
            v10 = lrelu(v10); v11 = lrelu(v11);
        }
        if (ROUND) {
            v00 = rtf(v00); v01 = rtf(v01);
            v10 = rtf(v10); v11 = rtf(v11);
        }
        if (r0 < M)
            *(float2*)(C + (size_t)r0 * ldC + lc) = make_float2(v00, v01);
        if (r1 < M)
            *(float2*)(C + (size_t)r1 * ldC + lc) = make_float2(v10, v11);
    }
}

// persistent single-W GEMM
template <bool LEAKY, bool ROUND>
__global__ void __launch_bounds__(512, 1) fw_gemm_p(
    const float* __restrict__ A, const uint32_t* __restrict__ W,
    const float* __restrict__ bias, float* __restrict__ C, int ldC, int M)
{
    extern __shared__ __align__(16) char sm[];
    const uint32_t sb = smem_u32(sm);
    const uint32_t bar_w = sb, bar_f0 = sb + 8, bar_f1 = sb + 16;
    const uint32_t ws_addr = sb + 128;
    const uint32_t as_addr = ws_addr + FW_W_BYTES;
    const uint2* Wsp = reinterpret_cast<const uint2*>(sm + 128);
    float (*As)[64][LD] = reinterpret_cast<float (*)[64][LD]>(sm + 128 + FW_W_BYTES);

    const int t = threadIdx.x;
    if (t == 0) {
        MBAR_INIT(bar_w, 1);
        MBAR_INIT(bar_f0, 1);
        MBAR_INIT(bar_f1, 1);
    }
    __syncthreads();
    if (t == 0) {
        MBAR_EXPECT(bar_w, FW_W_BYTES);
        bulkcp(ws_addr, W, FW_W_BYTES, bar_w);
    }

    const int ntiles = (M + 63) >> 6;
    int tiles[8];
    int nloc = 0;
    for (int tt = blockIdx.x; tt < ntiles; tt += gridDim.x) tiles[nloc++] = tt;

    auto issue = [&](int i) {
        if (i < nloc && t == 0) {
            uint32_t bar = (i & 1) ? bar_f1 : bar_f0;
            MBAR_EXPECT(bar, FW_TILE_BYTES);
            bulkcp(as_addr + (uint32_t)(i & 1) * FW_TILE_BYTES,
                   A + (size_t)tiles[i] * 64 * LD, FW_TILE_BYTES, bar);
        }
    };
    issue(0);
    issue(1);

    const int warp = t >> 5, lane = t & 31;
    const int mw = warp >> 2, nw = warp & 3;
    const int g = lane >> 2, tg = lane & 3;
    bool wdone = false;

    for (int i = 0; i < nloc; i++) {
        MBAR_WAITP((i & 1) ? bar_f1 : bar_f0, (i >> 1) & 1);
        if (!wdone) { MBAR_WAITP(bar_w, 0); wdone = true; }
        fw_tile_body<LEAKY, ROUND>(Wsp, As, i & 1, bias, C, ldC, M,
                                   tiles[i] * 64, mw, nw, g, tg);
        issue(i + 2);
    }
}

// persistent paired launch: half the grid does A@W1 -> C1, other half A@W2+bias2 -> C2
__global__ void __launch_bounds__(512, 1) fw_pair(
    const float* __restrict__ A,
    const uint32_t* __restrict__ W1, const uint32_t* __restrict__ W2,
    const float* __restrict__ bias2,
    float* __restrict__ C1, float* __restrict__ C2, int M)
{
    extern __shared__ __align__(16) char sm[];
    const uint32_t sb = smem_u32(sm);
    const uint32_t bar_w = sb, bar_f0 = sb + 8, bar_f1 = sb + 16;
    const uint32_t ws_addr = sb + 128;
    const uint32_t as_addr = ws_addr + FW_W_BYTES;
    const uint2* Wsp = reinterpret_cast<const uint2*>(sm + 128);
    float (*As)[64][LD] = reinterpret_cast<float (*)[64][LD]>(sm + 128 + FW_W_BYTES);

    const int half = (blockIdx.x >= 148) ? 1 : 0;
    const int bx = blockIdx.x - half * 148;
    const uint32_t* W = half ? W2 : W1;
    const float* bias = half ? bias2 : nullptr;
    float* C = half ? C2 : C1;

    const int t = threadIdx.x;
    if (t == 0) {
        MBAR_INIT(bar_w, 1);
        MBAR_INIT(bar_f0, 1);
        MBAR_INIT(bar_f1, 1);
    }
    __syncthreads();
    if (t == 0) {
        MBAR_EXPECT(bar_w, FW_W_BYTES);
        bulkcp(ws_addr, W, FW_W_BYTES, bar_w);
    }

    const int ntiles = (M + 63) >> 6;
    int tiles[8];
    int nloc = 0;
    for (int tt = bx; tt < ntiles; tt += 148) tiles[nloc++] = tt;

    auto issue = [&](int i) {
        if (i < nloc && t == 0) {
            uint32_t bar = (i & 1) ? bar_f1 : bar_f0;
            MBAR_EXPECT(bar, FW_TILE_BYTES);
            bulkcp(as_addr + (uint32_t)(i & 1) * FW_TILE_BYTES,
                   A + (size_t)tiles[i] * 64 * LD, FW_TILE_BYTES, bar);
        }
    };
    issue(0);
    issue(1);

    const int warp = t >> 5, lane = t & 31;
    const int mw = warp >> 2, nw = warp & 3;
    const int g = lane >> 2, tg = lane & 3;
    bool wdone = false;

    for (int i = 0; i < nloc; i++) {
        MBAR_WAITP((i & 1) ? bar_f1 : bar_f0, (i >> 1) & 1);
        if (!wdone) { MBAR_WAITP(bar_w, 0); wdone = true; }
        fw_tile_body<false, false>(Wsp, As, i & 1, bias, C, LD, M,
                                   tiles[i] * 64, mw, nw, g, tg);
        issue(i + 2);
    }
}

// fw_gemm_out: fw_gemm_p<true,false> with the 160->2 head fused into the epilogue.
// em (ldC=HID) gets leaky(A@W+bias); out[m,2] = em_row @ W_o2 + b_o2 (smem-reduced).
__global__ void __launch_bounds__(512, 1) fw_gemm_out(
    const float* __restrict__ A, const uint32_t* __restrict__ W,
    const float* __restrict__ bias, float* __restrict__ C, int M,
    const float* __restrict__ W2, const float* __restrict__ b2,
    float* __restrict__ out)
{
    extern __shared__ __align__(16) char sm[];
    const uint32_t sb = smem_u32(sm);
    const uint32_t bar_w = sb, bar_f0 = sb + 8, bar_f1 = sb + 16;
    const uint32_t ws_addr = sb + 128;
    const uint32_t as_addr = ws_addr + FW_W_BYTES;
    const uint2* Wsp = reinterpret_cast<const uint2*>(sm + 128);
    float (*As)[64][LD] = reinterpret_cast<float (*)[64][LD]>(sm + 128 + FW_W_BYTES);
    float (*sred)[64][17] = reinterpret_cast<float (*)[64][17]>(sm + FW_SMEM);

    const int t = threadIdx.x;
    if (t == 0) {
        MBAR_INIT(bar_w, 1);
        MBAR_INIT(bar_f0, 1);
        MBAR_INIT(bar_f1, 1);
    }
    __syncthreads();
    if (t == 0) {
        MBAR_EXPECT(bar_w, FW_W_BYTES);
        bulkcp(ws_addr, W, FW_W_BYTES, bar_w);
    }

    const int ntiles = (M + 63) >> 6;
    int tiles[8];
    int nloc = 0;
    for (int tt = blockIdx.x; tt < ntiles; tt += gridDim.x) tiles[nloc++] = tt;

    auto issue = [&](int i) {
        if (i < nloc && t == 0) {
            uint32_t bar = (i & 1) ? bar_f1 : bar_f0;
            MBAR_EXPECT(bar, FW_TILE_BYTES);
            bulkcp(as_addr + (uint32_t)(i & 1) * FW_TILE_BYTES,
                   A + (size_t)tiles[i] * 64 * LD, FW_TILE_BYTES, bar);
        }
    };
    issue(0);
    issue(1);

    const int warp = t >> 5, lane = t & 31;
    const int mw = warp >> 2, nw = warp & 3;
    const int g = lane >> 2, tg = lane & 3;
    const int ncol0 = nw * 40;
    const int wb = tg * WP2_LD + ncol0 + g;
    const int r = mw * 16 + g;
    bool wdone = false;

    // preload this thread's W_o2 entries: cols lc, lc+1 per nt
    float w2a[5][2], w2b[5][2];
    #pragma unroll
    for (int nt = 0; nt < 5; nt++) {
        int lc = ncol0 + nt * 8 + 2 * tg;
        w2a[nt][0] = W2[lc * 2];     w2a[nt][1] = W2[lc * 2 + 1];
        w2b[nt][0] = W2[lc * 2 + 2]; w2b[nt][1] = W2[lc * 2 + 3];
    }

    for (int i = 0; i < nloc; i++) {
        MBAR_WAITP((i & 1) ? bar_f1 : bar_f0, (i >> 1) & 1);
        if (!wdone) { MBAR_WAITP(bar_w, 0); wdone = true; }
        const int buf = i & 1;

        float acc[5][4] = {};
        #pragma unroll
        for (int kblk = 0; kblk < 20; kblk++) {
            const int kk = kblk * 8;
            uint32_t a0 = __float_as_uint(As[buf][r][kk + tg]);
            uint32_t a1 = __float_as_uint(As[buf][r + 8][kk + tg]);
            uint32_t a2 = __float_as_uint(As[buf][r][kk + tg + 4]);
            uint32_t a3 = __float_as_uint(As[buf][r + 8][kk + tg + 4]);
            const uint2* wrow = Wsp + kblk * (4 * WP2_LD) + wb;
            #pragma unroll
            for (int nt = 0; nt < 5; nt++) {
                uint2 bp = wrow[nt * 8];
                float* cc = acc[nt];
                asm volatile(
                    "mma.sync.aligned.m16n8k8.row.col.f32.tf32.tf32.f32 "
                    "{%0,%1,%2,%3}, {%4,%5,%6,%7}, {%8,%9}, {%0,%1,%2,%3};"
                    : "+f"(cc[0]), "+f"(cc[1]), "+f"(cc[2]), "+f"(cc[3])
                    : "r"(a0), "r"(a1), "r"(a2), "r"(a3), "r"(bp.x), "r"(bp.y));
            }
        }
        __syncthreads();
        issue(i + 2);

        const int tileRow = tiles[i] * 64;
        float p00 = 0.f, p01 = 0.f, p10 = 0.f, p11 = 0.f;   // [rowhalf][o]
        #pragma unroll
        for (int nt = 0; nt < 5; nt++) {
            int lc = ncol0 + nt * 8 + 2 * tg;
            float b0 = bias[lc];
            float b1 = bias[lc + 1];
            float* cc = acc[nt];
            int r0 = tileRow + mw * 16 + g;
            int r1 = r0 + 8;
            float v00 = lrelu(cc[0] + b0), v01 = lrelu(cc[1] + b1);
            float v10 = lrelu(cc[2] + b0), v11 = lrelu(cc[3] + b1);
            if (r0 < M)
                *(float2*)(C + (size_t)r0 * HID + lc) = make_float2(v00, v01);
            if (r1 < M)
                *(float2*)(C + (size_t)r1 * HID + lc) = make_float2(v10, v11);
            p00 += v00 * w2a[nt][0] + v01 * w2b[nt][0];
            p01 += v00 * w2a[nt][1] + v01 * w2b[nt][1];
            p10 += v10 * w2a[nt][0] + v11 * w2b[nt][0];
            p11 += v10 * w2a[nt][1] + v11 * w2b[nt][1];
        }
        const int lrow = mw * 16 + g;
        const int cidx = nw * 4 + tg;
        sred[0][lrow][cidx] = p00;
        sred[1][lrow][cidx] = p01;
        sred[0][lrow + 8][cidx] = p10;
        sred[1][lrow + 8][cidx] = p11;
        __syncthreads();
        if (t < 128) {
            int rr = t >> 1, o = t & 1;
            float s = 0.f;
            #pragma unroll
            for (int c = 0; c < 16; c++) s += sred[o][rr][c];
            int grow = tileRow + rr;
            if (grow < M) out[(size_t)grow * 2 + o] = s + b2[o];
        }
    }
}

// ============ projection GEMM (768->32): BK=128, 512 thr, split-K/4 ============
struct ProjArgs {
    const float* A[3];
    const uint32_t* W[3];   // padded [768][40]
    const float* b[3];
    int off[3];
};

#define PJ_AS_BYTES (128 * 132 * 4)     // 67584 per slot
#define PJ_WS_BYTES (128 * 40 * 4)      // 20480 per slot
#define PJ_SMEM (128 + 2 * PJ_AS_BYTES + 2 * PJ_WS_BYTES)   // 176256

__global__ void __launch_bounds__(512, 1) proj_kernel(ProjArgs pa, float* __restrict__ C, int M)
{
    extern __shared__ __align__(16) char sm[];
    const uint32_t sb = smem_u32(sm);
    const uint32_t bar_f0 = sb, bar_f1 = sb + 8;
    const uint32_t as_addr = sb + 128;
    const uint32_t ws_addr = as_addr + 2 * PJ_AS_BYTES;
    float (*As)[128][132] = reinterpret_cast<float (*)[128][132]>(sm + 128);
    uint32_t (*Ws)[128][40] = reinterpret_cast<uint32_t (*)[128][40]>(sm + 128 + 2 * PJ_AS_BYTES);

    const int z = blockIdx.z;
    const float* __restrict__ A = pa.A[z];
    const uint32_t* __restrict__ W = pa.W[z];
    const float* __restrict__ bias = pa.b[z];
    const int cOff = pa.off[z];

    const int t = threadIdx.x;
    const int blockRow = blockIdx.x * 128;
    const int nvalid = (M - blockRow) < 128 ? (M - blockRow) : 128;

    if (t == 0) { MBAR_INIT(bar_f0, 1); MBAR_INIT(bar_f1, 1); }
    __syncthreads();

    const int NCH = 6;   // K=768, BK=128
    auto issue = [&](int c) {
        if (c >= NCH) return;
        const int buf = c & 1;
        const uint32_t bar = buf ? bar_f1 : bar_f0;
        if (t == 0) MBAR_EXPECT(bar, (uint32_t)nvalid * 512 + PJ_WS_BYTES);
        if (t < 128 && t < nvalid) {
            int gr = blockRow + t;
            bulkcp(as_addr + (uint32_t)(buf * 128 + t) * (132 * 4),
                   A + (size_t)gr * 768 + c * 128, 512, bar);
        }
        if (t == 128) {
            bulkcp(ws_addr + (uint32_t)buf * PJ_WS_BYTES,
                   W + (size_t)c * 128 * 40, PJ_WS_BYTES, bar);
        }
    };
    issue(0);
    issue(1);

    const int warp = t >> 5;        // 0..15
    const int lane = t & 31;
    const int mwarp = warp & 3;
    const int kg = warp >> 2;       // 0..3
    const int g = lane >> 2;
    const int tg = lane & 3;
    const int warpRow = mwarp * 32;

    float acc[2][4][4] = {};

    for (int c = 0; c < NCH; c++) {
        MBAR_WAITP((c & 1) ? bar_f1 : bar_f0, (c >> 1) & 1);
        const int buf = c & 1;
        #pragma unroll
        for (int s = 0; s < 4; s++) {
            const int kk = kg * 32 + s * 8;
            uint32_t a[2][4];
            #pragma unroll
            for (int mt = 0; mt < 2; mt++) {
                const int r = warpRow + mt * 16 + g;
                a[mt][0] = f2tf32(As[buf][r][kk + tg]);
                a[mt][1] = f2tf32(As[buf][r + 8][kk + tg]);
                a[mt][2] = f2tf32(As[buf][r][kk + tg + 4]);
                a[mt][3] = f2tf32(As[buf][r + 8][kk + tg + 4]);
            }
            #pragma unroll
            for (int nt = 0; nt < 4; nt++) {
                uint32_t b0 = Ws[buf][kk + tg][nt * 8 + g];
                uint32_t b1 = Ws[buf][kk + tg + 4][nt * 8 + g];
                #pragma unroll
                for (int mt = 0; mt < 2; mt++) {
                    float* cc = acc[mt][nt];
                    asm volatile(
                        "mma.sync.aligned.m16n8k8.row.col.f32.tf32.tf32.f32 "
                        "{%0,%1,%2,%3}, {%4,%5,%6,%7}, {%8,%9}, {%0,%1,%2,%3};"
                        : "+f"(cc[0]), "+f"(cc[1]), "+f"(cc[2]), "+f"(cc[3])
                        : "r"(a[mt][0]), "r"(a[mt][1]), "r"(a[mt][2]), "r"(a[mt][3]),
                          "r"(b0), "r"(b1));
                }
            }
        }
        __syncthreads();     // all reads of buf done
        issue(c + 2);
    }

    // split-K/4 reduce: kg 1..3 write regions 0..2, kg0 sums (fixed order)
    float* scratch = &As[0][0][0];
    if (kg >= 1) {
        int base = (kg - 1) * 4096;
        #pragma unroll
        for (int mt = 0; mt < 2; mt++)
            #pragma unroll
            for (int nt = 0; nt < 4; nt++)
                #pragma unroll
                for (int i = 0; i < 4; i++) {
                    int combo = (mt * 4 + nt) * 4 + i;
                    scratch[base + combo * 128 + mwarp * 32 + lane] = acc[mt][nt][i];
                }
    }
    __syncthreads();

    if (kg == 0) {
        #pragma unroll
        for (int nt = 0; nt < 4; nt++) {
            int lc = nt * 8 + 2 * tg;
            float b0 = bias[lc];
            float b1 = bias[lc + 1];
            #pragma unroll
            for (int mt = 0; mt < 2; mt++) {
                float* cc = acc[mt][nt];
                int cb = ((mt * 4 + nt) * 4) * 128 + mwarp * 32 + lane;
                float s0 = ((cc[0] + scratch[cb])        + scratch[4096 + cb])        + scratch[8192 + cb];
                float s1 = ((cc[1] + scratch[cb + 128])  + scratch[4096 + cb + 128])  + scratch[8192 + cb + 128];
                float s2 = ((cc[2] + scratch[cb + 256])  + scratch[4096 + cb + 256])  + scratch[8192 + cb + 256];
                float s3 = ((cc[3] + scratch[cb + 384])  + scratch[4096 + cb + 384])  + scratch[8192 + cb + 384];
                float v00 = rtf(lrelu(s0 + b0));
                float v01 = rtf(lrelu(s1 + b1));
                float v10 = rtf(lrelu(s2 + b0));
                float v11 = rtf(lrelu(s3 + b1));
                int r0 = blockRow + warpRow + mt * 16 + g;
                int r1 = r0 + 8;
                if (r0 < M)
                    *(float2*)(C + (size_t)r0 * LD + cOff + lc) = make_float2(v00, v01);
                if (r1 < M)
                    *(float2*)(C + (size_t)r1 * LD + cOff + lc) = make_float2(v10, v11);
            }
        }
    }
}

// ---------------- small feature projections (tf32-rounded outputs) ----------------
__global__ void __launch_bounds__(256) feat_small_kernel(
    const float* __restrict__ np, const float* __restrict__ nc,
    const float* __restrict__ Wnp, const float* __restrict__ bnp,
    const float* __restrict__ Wnc, const float* __restrict__ bnc,
    float* __restrict__ out)
{
    __shared__ float sWnp[6 * 32];
    __shared__ float sWnc[11 * 32];
    __shared__ float sb[64];
    int t = threadIdx.x;
    for (int i = t; i < 192; i += 256) sWnp[i] = Wnp[i];
    for (int i = t; i < 352; i += 256) sWnc[i] = Wnc[i];
    if (t < 32) sb[t] = bnp[t];
    else if (t < 64) sb[t] = bnc[t - 32];
    __syncthreads();

    int node = blockIdx.x * 8 + (t >> 5);
    int lane = t & 31;
    if (node >= NN) return;

    float a = sb[lane], c = sb[32 + lane];
    #pragma unroll
    for (int k = 0; k < 6; k++) a += np[(size_t)node * 6 + k] * sWnp[k * 32 + lane];
    #pragma unroll
    for (int k = 0; k < 11; k++) c += nc[(size_t)node * 11 + k] * sWnc[k * 32 + lane];
    out[(size_t)node * LD + lane] = rtf(lrelu(a));
    out[(size_t)node * LD + 32 + lane] = rtf(lrelu(c));
}

// ---------------- CSR build ----------------
__global__ void zero_deg_kernel() {
    int i = blockIdx.x * blockDim.x + threadIdx.x;
    if (i < NN) g_deg[i] = 0;
}

__global__ void count_deg_kernel(const void* __restrict__ ei, int E) {
    int e = blockIdx.x * blockDim.x + threadIdx.x;
    if (e < E) atomicAdd(&g_deg[edge_val(ei, E + e)], 1);
}

__global__ void scan_kernel() {
    __shared__ int part[1024];
    int t = threadIdx.x;
    const int chunk = (NN + 1023) / 1024;
    int s0 = t * chunk;
    int s1 = s0 + chunk; if (s1 > NN) s1 = NN; if (s0 > NN) s0 = NN;
    int s = 0;
    for (int i = s0; i < s1; i++) s += g_deg[i];
    part[t] = s;
    __syncthreads();
    for (int d = 1; d < 1024; d <<= 1) {
        int v = (t >= d) ? part[t - d] : 0;
        __syncthreads();
        part[t] += v;
        __syncthreads();
    }
    int excl = t ? part[t - 1] : 0;
    for (int i = s0; i < s1; i++) {
        g_offs[i] = excl;
        g_cursor[i] = excl;
        excl += g_deg[i];
    }
    if (t == 1023) g_offs[NN] = part[1023];
}

__global__ void fill_csr_kernel(const void* __restrict__ ei, int E) {
    int e = blockIdx.x * blockDim.x + threadIdx.x;
    if (e < E) {
        int d = edge_val(ei, E + e);
        int p = atomicAdd(&g_cursor[d], 1);
        g_csr[p] = edge_val(ei, e);
    }
}

// -------- fused mean-aggregate + add (float4 gathers, 4-edge unroll) --------
__global__ void __launch_bounds__(256) agg_add_kernel(
    const float* __restrict__ t1, const float* __restrict__ t2,
    float* __restrict__ out)
{
    int w = (blockIdx.x * blockDim.x + threadIdx.x) >> 5;
    int lane = threadIdx.x & 31;
    if (w >= NN) return;
    int beg = g_offs[w], end = g_offs[w + 1];
    const bool tail = lane < 8;

    float4 s0 = make_float4(0.f, 0.f, 0.f, 0.f);
    float4 s1 = make_float4(0.f, 0.f, 0.f, 0.f);

    int e = beg;
    for (; e + 4 <= end; e += 4) {
        const float4* r0 = (const float4*)(t1 + (size_t)g_csr[e] * LD);
        const float4* r1 = (const float4*)(t1 + (size_t)g_csr[e + 1] * LD);
        const float4* r2 = (const float4*)(t1 + (size_t)g_csr[e + 2] * LD);
        const float4* r3 = (const float4*)(t1 + (size_t)g_csr[e + 3] * LD);
        float4 v0 = r0[lane], v1 = r1[lane], v2 = r2[lane], v3 = r3[lane];
        s0.x += (v0.x + v1.x) + (v2.x + v3.x);
        s0.y += (v0.y + v1.y) + (v2.y + v3.y);
        s0.z += (v0.z + v1.z) + (v2.z + v3.z);
        s0.w += (v0.w + v1.w) + (v2.w + v3.w);
        if (tail) {
            float4 u0 = r0[32 + lane], u1 = r1[32 + lane];
            float4 u2 = r2[32 + lane], u3 = r3[32 + lane];
            s1.x += (u0.x + u1.x) + (u2.x + u3.x);
            s1.y += (u0.y + u1.y) + (u2.y + u3.y);
            s1.z += (u0.z + u1.z) + (u2.z + u3.z);
            s1.w += (u0.w + u1.w) + (u2.w + u3.w);
        }
    }
    for (; e < end; e++) {
        const float4* ra = (const float4*)(t1 + (size_t)g_csr[e] * LD);
        float4 va = ra[lane];
        s0.x += va.x; s0.y += va.y; s0.z += va.z; s0.w += va.w;
        if (tail) {
            float4 ua = ra[32 + lane];
            s1.x += ua.x; s1.y += ua.y; s1.z += ua.z; s1.w += ua.w;
        }
    }

    int deg = end - beg;
    float inv = 1.f / (float)(deg > 0 ? deg : 1);
    const float4* b = (const float4*)(t2 + (size_t)w * LD);
    float4* m = (float4*)(out + (size_t)w * LD);

    float4 bv = b[lane];
    float4 o;
    o.x = rtf(s0.x * inv + bv.x);
    o.y = rtf(s0.y * inv + bv.y);
    o.z = rtf(s0.z * inv + bv.z);
    o.w = rtf(s0.w * inv + bv.w);
    m[lane] = o;
    if (tail) {
        float4 bu = b[32 + lane];
        float4 p;
        p.x = rtf(s1.x * inv + bu.x);
        p.y = rtf(s1.y * inv + bu.y);
        p.z = rtf(s1.z * inv + bu.z);
        p.w = rtf(s1.w * inv + bu.w);
        m[32 + lane] = p;
    }
}

// ---------------- launch ----------------
extern "C" void kernel_launch(void* const* d_in, const int* in_sizes, int n_in,
                              void* d_out, int out_size)
{
    const float* x        = (const float*)d_in[0];
    const void*  ei       = d_in[1];
    const float* num_prop = (const float*)d_in[2];
    const float* num_cat  = (const float*)d_in[3];
    const float* des      = (const float*)d_in[4];
    const float* tw       = (const float*)d_in[5];
    const float* W_des = (const float*)d_in[6];  const float* b_des = (const float*)d_in[7];
    const float* W_tw  = (const float*)d_in[8];  const float* b_tw  = (const float*)d_in[9];
    const float* W_txt = (const float*)d_in[10]; const float* b_txt = (const float*)d_in[11];
    const float* W_np  = (const float*)d_in[12]; const float* b_np  = (const float*)d_in[13];
    const float* W_nc  = (const float*)d_in[14]; const float* b_nc  = (const float*)d_in[15];
    const float* W_in  = (const float*)d_in[16]; const float* b_in  = (const float*)d_in[17];
    const float* W_l   = (const float*)d_in[18]; const float* b_l   = (const float*)d_in[19];
    const float* W_r   = (const float*)d_in[20];
    const float* W_o1  = (const float*)d_in[21]; const float* b_o1  = (const float*)d_in[22];
    const float* W_o2  = (const float*)d_in[23]; const float* b_o2  = (const float*)d_in[24];

    int E = in_sizes[1] / 2;
    if (E > EMAX) E = EMAX;

    float *feat, *h1, *mean, *h2;
    uint32_t* wtf;
    cudaGetSymbolAddress((void**)&feat, g_feat);
    cudaGetSymbolAddress((void**)&h1, g_h1);
    cudaGetSymbolAddress((void**)&mean, g_mean);
    cudaGetSymbolAddress((void**)&h2, g_h2);
    cudaGetSymbolAddress((void**)&wtf, g_wtf);

    float* outp = (float*)d_out;            // [N, 2]
    float* em   = (float*)d_out + 2 * NN;   // [N, 160], stride 160

    // weight preconversion
    WC wa;
    wa.src[0] = W_des; wa.src[1] = W_tw; wa.src[2] = W_txt;
    wa.src[3] = W_in;  wa.src[4] = W_l;  wa.src[5] = W_r; wa.src[6] = W_o1;
    int dense[7] = {24576, 24576, 24576, 25600, 25600, 25600, 25600};
    const int PJSZ = 768 * 40;   // 30720
    int dofs[7] = {0, PJSZ, 2 * PJSZ, 3 * PJSZ, 3 * PJSZ + HDSZ32,
                   3 * PJSZ + 2 * HDSZ32, 3 * PJSZ + 3 * HDSZ32};
    for (int s = 0; s < 7; s++) wa.doff[s] = dofs[s];
    wa.cum[0] = 0;
    for (int s = 0; s < 7; s++) wa.cum[s + 1] = wa.cum[s] + dense[s];
    const uint32_t* tWp_des = wtf + dofs[0];
    const uint32_t* tWp_tw  = wtf + dofs[1];
    const uint32_t* tWp_txt = wtf + dofs[2];
    const uint32_t* tW_in   = wtf + dofs[3];
    const uint32_t* tW_l    = wtf + dofs[4];
    const uint32_t* tW_r    = wtf + dofs[5];
    const uint32_t* tW_o1   = wtf + dofs[6];

    // one-time setup (runs on the uncaptured correctness call; reused in capture)
    static cudaStream_t s2 = nullptr;
    static cudaEvent_t evA = nullptr, evB = nullptr, evF = nullptr;
    if (!s2) {
        cudaStreamCreateWithFlags(&s2, cudaStreamNonBlocking);
        cudaEventCreateWithFlags(&evA, cudaEventDisableTiming);
        cudaEventCreateWithFlags(&evB, cudaEventDisableTiming);
        cudaEventCreateWithFlags(&evF, cudaEventDisableTiming);
        cudaFuncSetAttribute((const void*)fw_gemm_p<true, true>,
                             cudaFuncAttributeMaxDynamicSharedMemorySize, FW_SMEM);
        cudaFuncSetAttribute((const void*)fw_pair,
                             cudaFuncAttributeMaxDynamicSharedMemorySize, FW_SMEM);
        cudaFuncSetAttribute((const void*)fw_gemm_out,
                             cudaFuncAttributeMaxDynamicSharedMemorySize, FWO_SMEM);
        cudaFuncSetAttribute((const void*)proj_kernel,
                             cudaFuncAttributeMaxDynamicSharedMemorySize, PJ_SMEM);
    }

    dim3 gProj((NN + 127) / 128, 1, 3);
    int gP = 148;
    int gNode8 = (NN + 7) / 8;
    int gEdge = (E + 255) / 256;

    wconv_kernel<<<(wa.cum[7] + 255) / 256, 256>>>(wa);

    // fork: feat_small + CSR build on s2, overlapping proj below
    cudaEventRecord(evA, 0);
    cudaStreamWaitEvent(s2, evA, 0);
    feat_small_kernel<<<gNode8, 256, 0, s2>>>(num_prop, num_cat, W_np, b_np, W_nc, b_nc, feat);
    cudaEventRecord(evF, s2);
    detect_kernel<<<1, 256, 0, s2>>>(ei, E);
    zero_deg_kernel<<<(NN + 255) / 256, 256, 0, s2>>>();
    count_deg_kernel<<<gEdge, 256, 0, s2>>>(ei, E);
    scan_kernel<<<1, 1024, 0, s2>>>();
    fill_csr_kernel<<<gEdge, 256, 0, s2>>>(ei, E);
    cudaEventRecord(evB, s2);

    // proj -> feat cols 64..159 (disjoint from feat_small's cols 0..63)
    ProjArgs pa;
    pa.A[0] = des; pa.W[0] = tWp_des; pa.b[0] = b_des; pa.off[0] = 64;
    pa.A[1] = tw;  pa.W[1] = tWp_tw;  pa.b[1] = b_tw;  pa.off[1] = 96;
    pa.A[2] = x;   pa.W[2] = tWp_txt; pa.b[2] = b_txt; pa.off[2] = 128;
    proj_kernel<<<gProj, 512, PJ_SMEM>>>(pa, feat, NN);

    cudaStreamWaitEvent(0, evF, 0);   // feat cols 0..63 ready
    // h1 = rtf(leaky(feat @ W_in + b_in))
    fw_gemm_p<true, true><<<gP, 512, FW_SMEM>>>(feat, tW_in, b_in, h1, LD, NN);

    // conv1: h2 = rtf( mean_nbr(h1 @ W_l) + (h1 @ W_r + b_l) )
    fw_pair<<<2 * gP, 512, FW_SMEM>>>(h1, tW_l, tW_r, b_l, mean, feat, NN);
    cudaStreamWaitEvent(0, evB, 0);   // CSR ready before aggregation
    agg_add_kernel<<<gNode8, 256>>>(mean, feat, h2);

    // conv2: h1 = rtf( mean_nbr(h2 @ W_l) + (h2 @ W_r + b_l) )
    fw_pair<<<2 * gP, 512, FW_SMEM>>>(h2, tW_l, tW_r, b_l, mean, feat, NN);
    agg_add_kernel<<<gNode8, 256>>>(mean, feat, h1);

    // em = leaky(h1 @ W_o1 + b_o1) with fused 160->2 head -> out
    fw_gemm_out<<<gP, 512, FWO_SMEM>>>(h1, tW_o1, b_o1, em, NN, W_o2, b_o2, outp);
}

// round 15
// speedup vs baseline: 1.0509x; 1.0509x over previous
#include <cuda_runtime.h>
#include <cstdint>

#define NN 50000
#define NPAD 50048          // padded row count (782 * 64)
#define EMAX 500000
#define HID 160
#define LD 164              // row stride of intermediates: 164 % 32 == 4 -> conflict-free frags

#define WP2_LD 164          // paired hid-W row stride in uint2 units
#define HDSZ32 (80 * WP2_LD * 2)   // uint32 words per hid W (26240)

// ---------------- scratch (static device globals; no allocation) ----------------
__device__ float g_feat[NPAD * LD];
__device__ float g_h1[NPAD * LD];
__device__ float g_mean[NPAD * LD];
__device__ float g_h2[NPAD * LD];
__device__ int g_deg[NN];
__device__ int g_offs[NN + 1];
__device__ int g_cursor[NN];
__device__ int g_csr[EMAX];
__device__ int g_is64;
// weights: 3x proj padded [768][40] + 4x hid paired [80][164] uint2
__device__ uint32_t g_wtf[3 * 768 * 40 + 4 * HDSZ32];

__device__ __forceinline__ float lrelu(float x) { return x > 0.f ? x : 0.01f * x; }

__device__ __forceinline__ uint32_t f2tf32(float x) {
    uint32_t u;
    asm("cvt.rna.tf32.f32 %0, %1;" : "=r"(u) : "f"(x));
    return u;
}
__device__ __forceinline__ float rtf(float x) { return __uint_as_float(f2tf32(x)); }

__device__ __forceinline__ uint32_t smem_u32(const void* p) {
    return (uint32_t)__cvta_generic_to_shared(p);
}

// ---------------- mbarrier + bulk-copy primitives ----------------
#define MBAR_INIT(addr, cnt) \
    asm volatile("mbarrier.init.shared.b64 [%0], %1;" :: "r"(addr), "r"(cnt) : "memory")
#define MBAR_EXPECT(addr, bytes) \
    asm volatile("mbarrier.arrive.expect_tx.shared.b64 _, [%0], %1;" :: "r"(addr), "r"(bytes) : "memory")
#define MBAR_WAITP(addr, ph) do { \
    asm volatile( \
        "{\n\t.reg .pred P;\n" \
        "WAITL_%=:\n\t" \
        "mbarrier.try_wait.parity.acquire.cta.shared::cta.b64 P, [%0], %1, 0x989680;\n\t" \
        "@P bra.uni WAITD_%=;\n\t" \
        "bra.uni WAITL_%=;\n" \
        "WAITD_%=:\n\t}" \
        :: "r"(addr), "r"((uint32_t)(ph)) : "memory"); } while (0)

__device__ __forceinline__ void bulkcp(uint32_t dst_smem, const void* src,
                                       uint32_t bytes, uint32_t mbar) {
    asm volatile(
        "cp.async.bulk.shared::cluster.global.mbarrier::complete_tx::bytes "
        "[%0], [%1], %2, [%3];"
        :: "r"(dst_smem), "l"(src), "r"(bytes), "r"(mbar) : "memory");
}

// ---------------- weight preconversion ----------------
struct WC {
    const float* src[7];
    int doff[7], cum[8];
};

__global__ void wconv_kernel(WC a) {
    int i = blockIdx.x * 256 + threadIdx.x;
    #pragma unroll
    for (int s = 0; s < 7; s++) {
        if (i >= a.cum[s] && i < a.cum[s + 1]) {
            int j = i - a.cum[s];
            if (s < 3) {
                int row = j / 32, col = j % 32;
                g_wtf[a.doff[s] + row * 40 + col] = f2tf32(a.src[s][j]);
            } else {
                int row = j / 160, col = j % 160;
                int kblk = row >> 3, tg = row & 3, half = (row >> 2) & 1;
                int idx32 = a.doff[s] + ((kblk * 4 + tg) * WP2_LD + col) * 2 + half;
                g_wtf[idx32] = f2tf32(a.src[s][j]);
            }
        }
    }
}

// Edge index may be int64 (reference) or int32 (JAX canonicalization).
__device__ __forceinline__ int edge_val(const void* ei, int idx) {
    if (g_is64) return (int)((const long long*)ei)[idx];
    return ((const int*)ei)[idx];
}

__global__ void detect_kernel(const void* ei, int E) {
    __shared__ int any_hi;
    int t = threadIdx.x;
    if (t == 0) any_hi = 0;
    __syncthreads();
    const unsigned long long* p = (const unsigned long long*)ei;
    int n = E < 1024 ? E : 1024;
    unsigned long long acc = 0;
    for (int i = t; i < n; i += 256) acc |= p[i];
    if (acc > 0xFFFFFFFFull) atomicOr(&any_hi, 1);
    __syncthreads();
    if (t == 0) g_is64 = any_hi ? 0 : 1;
}

// ============ shared GEMM tile body (paired-k W, LDS.64 b-frags) ============
#define FW_W_BYTES (HDSZ32 * 4)             // 104960
#define FW_TILE_BYTES (64 * LD * 4)         // 41984
#define FW_SMEM (128 + FW_W_BYTES + 2 * FW_TILE_BYTES)   // 189056
#define FWO_SMEM (FW_SMEM + 2 * 64 * 17 * 4)             // +8704 = 197760

template <bool LEAKY, bool ROUND>
__device__ __forceinline__ void fw_tile_body(
    const uint2* Wsp, const float (*As)[64][LD], int buf,
    const float* bias, float* C, int ldC, int M, int tileRow,
    int mw, int nw, int g, int tg)
{
    const int ncol0 = nw * 40;
    const int wb = tg * WP2_LD + ncol0 + g;
    const int r = mw * 16 + g;

    float acc[5][4] = {};
    #pragma unroll
    for (int kblk = 0; kblk < 20; kblk++) {
        const int kk = kblk * 8;
        uint32_t a0 = __float_as_uint(As[buf][r][kk + tg]);
        uint32_t a1 = __float_as_uint(As[buf][r + 8][kk + tg]);
        uint32_t a2 = __float_as_uint(As[buf][r][kk + tg + 4]);
        uint32_t a3 = __float_as_uint(As[buf][r + 8][kk + tg + 4]);
        const uint2* wrow = Wsp + kblk * (4 * WP2_LD) + wb;
        #pragma unroll
        for (int nt = 0; nt < 5; nt++) {
            uint2 bp = wrow[nt * 8];
            float* cc = acc[nt];
            asm volatile(
                "mma.sync.aligned.m16n8k8.row.col.f32.tf32.tf32.f32 "
                "{%0,%1,%2,%3}, {%4,%5,%6,%7}, {%8,%9}, {%0,%1,%2,%3};"
                : "+f"(cc[0]), "+f"(cc[1]), "+f"(cc[2]), "+f"(cc[3])
                : "r"(a0), "r"(a1), "r"(a2), "r"(a3), "r"(bp.x), "r"(bp.y));
        }
    }
    __syncthreads();   // all reads of buf done (caller may refill after)

    #pragma unroll
    for (int nt = 0; nt < 5; nt++) {
        int lc = ncol0 + nt * 8 + 2 * tg;
        float b0 = bias ? bias[lc] : 0.f;
        float b1 = bias ? bias[lc + 1] : 0.f;
        float* cc = acc[nt];
        int r0 = tileRow + mw * 16 + g;
        int r1 = r0 + 8;
        float v00 = cc[0] + b0, v01 = cc[1] + b1;
        float v10 = cc[2] + b0, v11 = cc[3] + b1;
        if (LEAKY) {
            v00 = lrelu(v00); v01 = lrelu(v01);
            v10 = lrelu(v10); v11 = lrelu(v11);
        }
        if (ROUND) {
            v00 = rtf(v00); v01 = rtf(v01);
            v10 = rtf(v10); v11 = rtf(v11);
        }
        if (r0 < M)
            *(float2*)(C + (size_t)r0 * ldC + lc) = make_float2(v00, v01);
        if (r1 < M)
            *(float2*)(C + (size_t)r1 * ldC + lc) = make_float2(v10, v11);
    }
}

// persistent single-W GEMM
template <bool LEAKY, bool ROUND>
__global__ void __launch_bounds__(512, 1) fw_gemm_p(
    const float* __restrict__ A, const uint32_t* __restrict__ W,
    const float* __restrict__ bias, float* __restrict__ C, int ldC, int M)
{
    extern __shared__ __align__(16) char sm[];
    const uint32_t sb = smem_u32(sm);
    const uint32_t bar_w = sb, bar_f0 = sb + 8, bar_f1 = sb + 16;
    const uint32_t ws_addr = sb + 128;
    const uint32_t as_addr = ws_addr + FW_W_BYTES;
    const uint2* Wsp = reinterpret_cast<const uint2*>(sm + 128);
    float (*As)[64][LD] = reinterpret_cast<float (*)[64][LD]>(sm + 128 + FW_W_BYTES);

    const int t = threadIdx.x;
    if (t == 0) {
        MBAR_INIT(bar_w, 1);
        MBAR_INIT(bar_f0, 1);
        MBAR_INIT(bar_f1, 1);
    }
    __syncthreads();
    if (t == 0) {
        MBAR_EXPECT(bar_w, FW_W_BYTES);
        bulkcp(ws_addr, W, FW_W_BYTES, bar_w);
    }

    const int ntiles = (M + 63) >> 6;
    int tiles[8];
    int nloc = 0;
    for (int tt = blockIdx.x; tt < ntiles; tt += gridDim.x) tiles[nloc++] = tt;

    auto issue = [&](int i) {
        if (i < nloc && t == 0) {
            uint32_t bar = (i & 1) ? bar_f1 : bar_f0;
            MBAR_EXPECT(bar, FW_TILE_BYTES);
            bulkcp(as_addr + (uint32_t)(i & 1) * FW_TILE_BYTES,
                   A + (size_t)tiles[i] * 64 * LD, FW_TILE_BYTES, bar);
        }
    };
    issue(0);
    issue(1);

    const int warp = t >> 5, lane = t & 31;
    const int mw = warp >> 2, nw = warp & 3;
    const int g = lane >> 2, tg = lane & 3;
    bool wdone = false;

    for (int i = 0; i < nloc; i++) {
        MBAR_WAITP((i & 1) ? bar_f1 : bar_f0, (i >> 1) & 1);
        if (!wdone) { MBAR_WAITP(bar_w, 0); wdone = true; }
        fw_tile_body<LEAKY, ROUND>(Wsp, As, i & 1, bias, C, ldC, M,
                                   tiles[i] * 64, mw, nw, g, tg);
        issue(i + 2);
    }
}

// persistent paired launch: half the grid does A@W1 -> C1, other half A@W2+bias2 -> C2
__global__ void __launch_bounds__(512, 1) fw_pair(
    const float* __restrict__ A,
    const uint32_t* __restrict__ W1, const uint32_t* __restrict__ W2,
    const float* __restrict__ bias2,
    float* __restrict__ C1, float* __restrict__ C2, int M)
{
    extern __shared__ __align__(16) char sm[];
    const uint32_t sb = smem_u32(sm);
    const uint32_t bar_w = sb, bar_f0 = sb + 8, bar_f1 = sb + 16;
    const uint32_t ws_addr = sb + 128;
    const uint32_t as_addr = ws_addr + FW_W_BYTES;
    const uint2* Wsp = reinterpret_cast<const uint2*>(sm + 128);
    float (*As)[64][LD] = reinterpret_cast<float (*)[64][LD]>(sm + 128 + FW_W_BYTES);

    const int half = (blockIdx.x >= 148) ? 1 : 0;
    const int bx = blockIdx.x - half * 148;
    const uint32_t* W = half ? W2 : W1;
    const float* bias = half ? bias2 : nullptr;
    float* C = half ? C2 : C1;

    const int t = threadIdx.x;
    if (t == 0) {
        MBAR_INIT(bar_w, 1);
        MBAR_INIT(bar_f0, 1);
        MBAR_INIT(bar_f1, 1);
    }
    __syncthreads();
    if (t == 0) {
        MBAR_EXPECT(bar_w, FW_W_BYTES);
        bulkcp(ws_addr, W, FW_W_BYTES, bar_w);
    }

    const int ntiles = (M + 63) >> 6;
    int tiles[8];
    int nloc = 0;
    for (int tt = bx; tt < ntiles; tt += 148) tiles[nloc++] = tt;

    auto issue = [&](int i) {
        if (i < nloc && t == 0) {
            uint32_t bar = (i & 1) ? bar_f1 : bar_f0;
            MBAR_EXPECT(bar, FW_TILE_BYTES);
            bulkcp(as_addr + (uint32_t)(i & 1) * FW_TILE_BYTES,
                   A + (size_t)tiles[i] * 64 * LD, FW_TILE_BYTES, bar);
        }
    };
    issue(0);
    issue(1);

    const int warp = t >> 5, lane = t & 31;
    const int mw = warp >> 2, nw = warp & 3;
    const int g = lane >> 2, tg = lane & 3;
    bool wdone = false;

    for (int i = 0; i < nloc; i++) {
        MBAR_WAITP((i & 1) ? bar_f1 : bar_f0, (i >> 1) & 1);
        if (!wdone) { MBAR_WAITP(bar_w, 0); wdone = true; }
        fw_tile_body<false, false>(Wsp, As, i & 1, bias, C, LD, M,
                                   tiles[i] * 64, mw, nw, g, tg);
        issue(i + 2);
    }
}

// fw_gemm_out: fw_gemm_p<true,false> with the 160->2 head fused into the epilogue.
// em (ldC=HID) gets leaky(A@W+bias); out[m,2] = em_row @ W_o2 + b_o2 (smem-reduced).
__global__ void __launch_bounds__(512, 1) fw_gemm_out(
    const float* __restrict__ A, const uint32_t* __restrict__ W,
    const float* __restrict__ bias, float* __restrict__ C, int M,
    const float* __restrict__ W2, const float* __restrict__ b2,
    float* __restrict__ out)
{
    extern __shared__ __align__(16) char sm[];
    const uint32_t sb = smem_u32(sm);
    const uint32_t bar_w = sb, bar_f0 = sb + 8, bar_f1 = sb + 16;
    const uint32_t ws_addr = sb + 128;
    const uint32_t as_addr = ws_addr + FW_W_BYTES;
    const uint2* Wsp = reinterpret_cast<const uint2*>(sm + 128);
    float (*As)[64][LD] = reinterpret_cast<float (*)[64][LD]>(sm + 128 + FW_W_BYTES);
    float (*sred)[64][17] = reinterpret_cast<float (*)[64][17]>(sm + FW_SMEM);

    const int t = threadIdx.x;
    if (t == 0) {
        MBAR_INIT(bar_w, 1);
        MBAR_INIT(bar_f0, 1);
        MBAR_INIT(bar_f1, 1);
    }
    __syncthreads();
    if (t == 0) {
        MBAR_EXPECT(bar_w, FW_W_BYTES);
        bulkcp(ws_addr, W, FW_W_BYTES, bar_w);
    }

    const int ntiles = (M + 63) >> 6;
    int tiles[8];
    int nloc = 0;
    for (int tt = blockIdx.x; tt < ntiles; tt += gridDim.x) tiles[nloc++] = tt;

    auto issue = [&](int i) {
        if (i < nloc && t == 0) {
            uint32_t bar = (i & 1) ? bar_f1 : bar_f0;
            MBAR_EXPECT(bar, FW_TILE_BYTES);
            bulkcp(as_addr + (uint32_t)(i & 1) * FW_TILE_BYTES,
                   A + (size_t)tiles[i] * 64 * LD, FW_TILE_BYTES, bar);
        }
    };
    issue(0);
    issue(1);

    const int warp = t >> 5, lane = t & 31;
    const int mw = warp >> 2, nw = warp & 3;
    const int g = lane >> 2, tg = lane & 3;
    const int ncol0 = nw * 40;
    const int wb = tg * WP2_LD + ncol0 + g;
    const int r = mw * 16 + g;
    bool wdone = false;

    // preload this thread's W_o2 entries: cols lc, lc+1 per nt
    float w2a[5][2], w2b[5][2];
    #pragma unroll
    for (int nt = 0; nt < 5; nt++) {
        int lc = ncol0 + nt * 8 + 2 * tg;
        w2a[nt][0] = W2[lc * 2];     w2a[nt][1] = W2[lc * 2 + 1];
        w2b[nt][0] = W2[lc * 2 + 2]; w2b[nt][1] = W2[lc * 2 + 3];
    }

    for (int i = 0; i < nloc; i++) {
        MBAR_WAITP((i & 1) ? bar_f1 : bar_f0, (i >> 1) & 1);
        if (!wdone) { MBAR_WAITP(bar_w, 0); wdone = true; }
        const int buf = i & 1;

        float acc[5][4] = {};
        #pragma unroll
        for (int kblk = 0; kblk < 20; kblk++) {
            const int kk = kblk * 8;
            uint32_t a0 = __float_as_uint(As[buf][r][kk + tg]);
            uint32_t a1 = __float_as_uint(As[buf][r + 8][kk + tg]);
            uint32_t a2 = __float_as_uint(As[buf][r][kk + tg + 4]);
            uint32_t a3 = __float_as_uint(As[buf][r + 8][kk + tg + 4]);
            const uint2* wrow = Wsp + kblk * (4 * WP2_LD) + wb;
            #pragma unroll
            for (int nt = 0; nt < 5; nt++) {
                uint2 bp = wrow[nt * 8];
                float* cc = acc[nt];
                asm volatile(
                    "mma.sync.aligned.m16n8k8.row.col.f32.tf32.tf32.f32 "
                    "{%0,%1,%2,%3}, {%4,%5,%6,%7}, {%8,%9}, {%0,%1,%2,%3};"
                    : "+f"(cc[0]), "+f"(cc[1]), "+f"(cc[2]), "+f"(cc[3])
                    : "r"(a0), "r"(a1), "r"(a2), "r"(a3), "r"(bp.x), "r"(bp.y));
            }
        }
        __syncthreads();
        issue(i + 2);

        const int tileRow = tiles[i] * 64;
        float p00 = 0.f, p01 = 0.f, p10 = 0.f, p11 = 0.f;   // [rowhalf][o]
        #pragma unroll
        for (int nt = 0; nt < 5; nt++) {
            int lc = ncol0 + nt * 8 + 2 * tg;
            float b0 = bias[lc];
            float b1 = bias[lc + 1];
            float* cc = acc[nt];
            int r0 = tileRow + mw * 16 + g;
            int r1 = r0 + 8;
            float v00 = lrelu(cc[0] + b0), v01 = lrelu(cc[1] + b1);
            float v10 = lrelu(cc[2] + b0), v11 = lrelu(cc[3] + b1);
            if (r0 < M)
                *(float2*)(C + (size_t)r0 * HID + lc) = make_float2(v00, v01);
            if (r1 < M)
                *(float2*)(C + (size_t)r1 * HID + lc) = make_float2(v10, v11);
            p00 += v00 * w2a[nt][0] + v01 * w2b[nt][0];
            p01 += v00 * w2a[nt][1] + v01 * w2b[nt][1];
            p10 += v10 * w2a[nt][0] + v11 * w2b[nt][0];
            p11 += v10 * w2a[nt][1] + v11 * w2b[nt][1];
        }
        const int lrow = mw * 16 + g;
        const int cidx = nw * 4 + tg;
        sred[0][lrow][cidx] = p00;
        sred[1][lrow][cidx] = p01;
        sred[0][lrow + 8][cidx] = p10;
        sred[1][lrow + 8][cidx] = p11;
        __syncthreads();
        if (t < 128) {
            int rr = t >> 1, o = t & 1;
            float s = 0.f;
            #pragma unroll
            for (int c = 0; c < 16; c++) s += sred[o][rr][c];
            int grow = tileRow + rr;
            if (grow < M) out[(size_t)grow * 2 + o] = s + b2[o];
        }
    }
}

// ============ projection GEMM (768->32): bulk loads, BK=64, split-K (round-13) ============
struct ProjArgs {
    const float* A[3];
    const uint32_t* W[3];   // padded [768][40]
    const float* b[3];
    int off[3];
};

#define PJ_AS_BYTES (128 * 68 * 4)      // 34816 per slot
#define PJ_WS_BYTES (64 * 40 * 4)       // 10240 per slot
#define PJ_SMEM (128 + 2 * PJ_AS_BYTES + 2 * PJ_WS_BYTES)   // 90240

__global__ void __launch_bounds__(256) proj_kernel(ProjArgs pa, float* __restrict__ C, int M)
{
    extern __shared__ __align__(16) char sm[];
    const uint32_t sb = smem_u32(sm);
    const uint32_t bar_f0 = sb, bar_f1 = sb + 8;
    const uint32_t as_addr = sb + 128;
    const uint32_t ws_addr = as_addr + 2 * PJ_AS_BYTES;
    float (*As)[128][68] = reinterpret_cast<float (*)[128][68]>(sm + 128);
    uint32_t (*Ws)[64][40] = reinterpret_cast<uint32_t (*)[64][40]>(sm + 128 + 2 * PJ_AS_BYTES);

    const int z = blockIdx.z;
    const float* __restrict__ A = pa.A[z];
    const uint32_t* __restrict__ W = pa.W[z];
    const float* __restrict__ bias = pa.b[z];
    const int cOff = pa.off[z];

    const int t = threadIdx.x;
    const int blockRow = blockIdx.x * 128;
    const int nvalid = (M - blockRow) < 128 ? (M - blockRow) : 128;

    if (t == 0) { MBAR_INIT(bar_f0, 1); MBAR_INIT(bar_f1, 1); }
    __syncthreads();

    const int NCH = 12;   // K=768, BK=64
    auto issue = [&](int c) {
        if (c >= NCH) return;
        const int buf = c & 1;
        const uint32_t bar = buf ? bar_f1 : bar_f0;
        if (t == 0) MBAR_EXPECT(bar, (uint32_t)nvalid * 256 + PJ_WS_BYTES);
        if (t < 128 && t < nvalid) {
            int gr = blockRow + t;
            bulkcp(as_addr + (uint32_t)(buf * 128 + t) * (68 * 4),
                   A + (size_t)gr * 768 + c * 64, 256, bar);
        }
        if (t == 128) {
            bulkcp(ws_addr + (uint32_t)buf * PJ_WS_BYTES,
                   W + (size_t)c * 64 * 40, PJ_WS_BYTES, bar);
        }
    };
    issue(0);
    issue(1);

    const int warp = t >> 5;
    const int lane = t & 31;
    const int mwarp = warp & 3;
    const int kg = warp >> 2;
    const int g = lane >> 2;
    const int tg = lane & 3;
    const int warpRow = mwarp * 32;

    float acc[2][4][4] = {};

    for (int c = 0; c < NCH; c++) {
        MBAR_WAITP((c & 1) ? bar_f1 : bar_f0, (c >> 1) & 1);
        const int buf = c & 1;
        #pragma unroll
        for (int s = 0; s < 2; s++) {
            const int kk = kg * 32 + s * 8;
            uint32_t a[2][4];
            #pragma unroll
            for (int mt = 0; mt < 2; mt++) {
                const int r = warpRow + mt * 16 + g;
                a[mt][0] = f2tf32(As[buf][r][kk + tg]);
                a[mt][1] = f2tf32(As[buf][r + 8][kk + tg]);
                a[mt][2] = f2tf32(As[buf][r][kk + tg + 4]);
                a[mt][3] = f2tf32(As[buf][r + 8][kk + tg + 4]);
            }
            #pragma unroll
            for (int nt = 0; nt < 4; nt++) {
                uint32_t b0 = Ws[buf][kk + tg][nt * 8 + g];
                uint32_t b1 = Ws[buf][kk + tg + 4][nt * 8 + g];
                #pragma unroll
                for (int mt = 0; mt < 2; mt++) {
                    float* cc = acc[mt][nt];
                    asm volatile(
                        "mma.sync.aligned.m16n8k8.row.col.f32.tf32.tf32.f32 "
                        "{%0,%1,%2,%3}, {%4,%5,%6,%7}, {%8,%9}, {%0,%1,%2,%3};"
                        : "+f"(cc[0]), "+f"(cc[1]), "+f"(cc[2]), "+f"(cc[3])
                        : "r"(a[mt][0]), "r"(a[mt][1]), "r"(a[mt][2]), "r"(a[mt][3]),
                          "r"(b0), "r"(b1));
                }
            }
        }
        #pragma unroll
        for (int s = 2; s < 4; s++) {
            const int kk = kg * 32 + s * 8;
            uint32_t a[2][4];
            #pragma unroll
            for (int mt = 0; mt < 2; mt++) {
                const int r = warpRow + mt * 16 + g;
                a[mt][0] = f2tf32(As[buf][r][kk + tg]);
                a[mt][1] = f2tf32(As[buf][r + 8][kk + tg]);
                a[mt][2] = f2tf32(As[buf][r][kk + tg + 4]);
                a[mt][3] = f2tf32(As[buf][r + 8][kk + tg + 4]);
            }
            #pragma unroll
            for (int nt = 0; nt < 4; nt++) {
                uint32_t b0 = Ws[buf][kk + tg][nt * 8 + g];
                uint32_t b1 = Ws[buf][kk + tg + 4][nt * 8 + g];
                #pragma unroll
                for (int mt = 0; mt < 2; mt++) {
                    float* cc = acc[mt][nt];
                    asm volatile(
                        "mma.sync.aligned.m16n8k8.row.col.f32.tf32.tf32.f32 "
                        "{%0,%1,%2,%3}, {%4,%5,%6,%7}, {%8,%9}, {%0,%1,%2,%3};"
                        : "+f"(cc[0]), "+f"(cc[1]), "+f"(cc[2]), "+f"(cc[3])
                        : "r"(a[mt][0]), "r"(a[mt][1]), "r"(a[mt][2]), "r"(a[mt][3]),
                          "r"(b0), "r"(b1));
                }
            }
        }
        __syncthreads();     // all reads of buf done
        issue(c + 2);
    }

    float* scratch = &As[0][0][0];
    if (kg == 1) {
        #pragma unroll
        for (int mt = 0; mt < 2; mt++)
            #pragma unroll
            for (int nt = 0; nt < 4; nt++)
                #pragma unroll
                for (int i = 0; i < 4; i++) {
                    int combo = (mt * 4 + nt) * 4 + i;
                    scratch[combo * 128 + mwarp * 32 + lane] = acc[mt][nt][i];
                }
    }
    __syncthreads();

    if (kg == 0) {
        #pragma unroll
        for (int nt = 0; nt < 4; nt++) {
            int lc = nt * 8 + 2 * tg;
            float b0 = bias[lc];
            float b1 = bias[lc + 1];
            #pragma unroll
            for (int mt = 0; mt < 2; mt++) {
                float* cc = acc[mt][nt];
                int base = ((mt * 4 + nt) * 4) * 128 + mwarp * 32 + lane;
                float v00 = rtf(lrelu(cc[0] + scratch[base]       + b0));
                float v01 = rtf(lrelu(cc[1] + scratch[base + 128] + b1));
                float v10 = rtf(lrelu(cc[2] + scratch[base + 256] + b0));
                float v11 = rtf(lrelu(cc[3] + scratch[base + 384] + b1));
                int r0 = blockRow + warpRow + mt * 16 + g;
                int r1 = r0 + 8;
                if (r0 < M)
                    *(float2*)(C + (size_t)r0 * LD + cOff + lc) = make_float2(v00, v01);
                if (r1 < M)
                    *(float2*)(C + (size_t)r1 * LD + cOff + lc) = make_float2(v10, v11);
            }
        }
    }
}

// ---------------- small feature projections (tf32-rounded outputs) ----------------
__global__ void __launch_bounds__(256) feat_small_kernel(
    const float* __restrict__ np, const float* __restrict__ nc,
    const float* __restrict__ Wnp, const float* __restrict__ bnp,
    const float* __restrict__ Wnc, const float* __restrict__ bnc,
    float* __restrict__ out)
{
    __shared__ float sWnp[6 * 32];
    __shared__ float sWnc[11 * 32];
    __shared__ float sb[64];
    int t = threadIdx.x;
    for (int i = t; i < 192; i += 256) sWnp[i] = Wnp[i];
    for (int i = t; i < 352; i += 256) sWnc[i] = Wnc[i];
    if (t < 32) sb[t] = bnp[t];
    else if (t < 64) sb[t] = bnc[t - 32];
    __syncthreads();

    int node = blockIdx.x * 8 + (t >> 5);
    int lane = t & 31;
    if (node >= NN) return;

    float a = sb[lane], c = sb[32 + lane];
    #pragma unroll
    for (int k = 0; k < 6; k++) a += np[(size_t)node * 6 + k] * sWnp[k * 32 + lane];
    #pragma unroll
    for (int k = 0; k < 11; k++) c += nc[(size_t)node * 11 + k] * sWnc[k * 32 + lane];
    out[(size_t)node * LD + lane] = rtf(lrelu(a));
    out[(size_t)node * LD + 32 + lane] = rtf(lrelu(c));
}

// ---------------- CSR build ----------------
__global__ void zero_deg_kernel() {
    int i = blockIdx.x * blockDim.x + threadIdx.x;
    if (i < NN) g_deg[i] = 0;
}

__global__ void count_deg_kernel(const void* __restrict__ ei, int E) {
    int e = blockIdx.x * blockDim.x + threadIdx.x;
    if (e < E) atomicAdd(&g_deg[edge_val(ei, E + e)], 1);
}

__global__ void scan_kernel() {
    __shared__ int part[1024];
    int t = threadIdx.x;
    const int chunk = (NN + 1023) / 1024;
    int s0 = t * chunk;
    int s1 = s0 + chunk; if (s1 > NN) s1 = NN; if (s0 > NN) s0 = NN;
    int s = 0;
    for (int i = s0; i < s1; i++) s += g_deg[i];
    part[t] = s;
    __syncthreads();
    for (int d = 1; d < 1024; d <<= 1) {
        int v = (t >= d) ? part[t - d] : 0;
        __syncthreads();
        part[t] += v;
        __syncthreads();
    }
    int excl = t ? part[t - 1] : 0;
    for (int i = s0; i < s1; i++) {
        g_offs[i] = excl;
        g_cursor[i] = excl;
        excl += g_deg[i];
    }
    if (t == 1023) g_offs[NN] = part[1023];
}

__global__ void fill_csr_kernel(const void* __restrict__ ei, int E) {
    int e = blockIdx.x * blockDim.x + threadIdx.x;
    if (e < E) {
        int d = edge_val(ei, E + e);
        int p = atomicAdd(&g_cursor[d], 1);
        g_csr[p] = edge_val(ei, e);
    }
}

// -------- fused mean-aggregate + add (float4 gathers, 4-edge unroll) --------
__global__ void __launch_bounds__(256) agg_add_kernel(
    const float* __restrict__ t1, const float* __restrict__ t2,
    float* __restrict__ out)
{
    int w = (blockIdx.x * blockDim.x + threadIdx.x) >> 5;
    int lane = threadIdx.x & 31;
    if (w >= NN) return;
    int beg = g_offs[w], end = g_offs[w + 1];
    const bool tail = lane < 8;

    float4 s0 = make_float4(0.f, 0.f, 0.f, 0.f);
    float4 s1 = make_float4(0.f, 0.f, 0.f, 0.f);

    int e = beg;
    for (; e + 4 <= end; e += 4) {
        const float4* r0 = (const float4*)(t1 + (size_t)g_csr[e] * LD);
        const float4* r1 = (const float4*)(t1 + (size_t)g_csr[e + 1] * LD);
        const float4* r2 = (const float4*)(t1 + (size_t)g_csr[e + 2] * LD);
        const float4* r3 = (const float4*)(t1 + (size_t)g_csr[e + 3] * LD);
        float4 v0 = r0[lane], v1 = r1[lane], v2 = r2[lane], v3 = r3[lane];
        s0.x += (v0.x + v1.x) + (v2.x + v3.x);
        s0.y += (v0.y + v1.y) + (v2.y + v3.y);
        s0.z += (v0.z + v1.z) + (v2.z + v3.z);
        s0.w += (v0.w + v1.w) + (v2.w + v3.w);
        if (tail) {
            float4 u0 = r0[32 + lane], u1 = r1[32 + lane];
            float4 u2 = r2[32 + lane], u3 = r3[32 + lane];
            s1.x += (u0.x + u1.x) + (u2.x + u3.x);
            s1.y += (u0.y + u1.y) + (u2.y + u3.y);
            s1.z += (u0.z + u1.z) + (u2.z + u3.z);
            s1.w += (u0.w + u1.w) + (u2.w + u3.w);
        }
    }
    for (; e < end; e++) {
        const float4* ra = (const float4*)(t1 + (size_t)g_csr[e] * LD);
        float4 va = ra[lane];
        s0.x += va.x; s0.y += va.y; s0.z += va.z; s0.w += va.w;
        if (tail) {
            float4 ua = ra[32 + lane];
            s1.x += ua.x; s1.y += ua.y; s1.z += ua.z; s1.w += ua.w;
        }
    }

    int deg = end - beg;
    float inv = 1.f / (float)(deg > 0 ? deg : 1);
    const float4* b = (const float4*)(t2 + (size_t)w * LD);
    float4* m = (float4*)(out + (size_t)w * LD);

    float4 bv = b[lane];
    float4 o;
    o.x = rtf(s0.x * inv + bv.x);
    o.y = rtf(s0.y * inv + bv.y);
    o.z = rtf(s0.z * inv + bv.z);
    o.w = rtf(s0.w * inv + bv.w);
    m[lane] = o;
    if (tail) {
        float4 bu = b[32 + lane];
        float4 p;
        p.x = rtf(s1.x * inv + bu.x);
        p.y = rtf(s1.y * inv + bu.y);
        p.z = rtf(s1.z * inv + bu.z);
        p.w = rtf(s1.w * inv + bu.w);
        m[32 + lane] = p;
    }
}

// ---------------- launch ----------------
extern "C" void kernel_launch(void* const* d_in, const int* in_sizes, int n_in,
                              void* d_out, int out_size)
{
    const float* x        = (const float*)d_in[0];
    const void*  ei       = d_in[1];
    const float* num_prop = (const float*)d_in[2];
    const float* num_cat  = (const float*)d_in[3];
    const float* des      = (const float*)d_in[4];
    const float* tw       = (const float*)d_in[5];
    const float* W_des = (const float*)d_in[6];  const float* b_des = (const float*)d_in[7];
    const float* W_tw  = (const float*)d_in[8];  const float* b_tw  = (const float*)d_in[9];
    const float* W_txt = (const float*)d_in[10]; const float* b_txt = (const float*)d_in[11];
    const float* W_np  = (const float*)d_in[12]; const float* b_np  = (const float*)d_in[13];
    const float* W_nc  = (const float*)d_in[14]; const float* b_nc  = (const float*)d_in[15];
    const float* W_in  = (const float*)d_in[16]; const float* b_in  = (const float*)d_in[17];
    const float* W_l   = (const float*)d_in[18]; const float* b_l   = (const float*)d_in[19];
    const float* W_r   = (const float*)d_in[20];
    const float* W_o1  = (const float*)d_in[21]; const float* b_o1  = (const float*)d_in[22];
    const float* W_o2  = (const float*)d_in[23]; const float* b_o2  = (const float*)d_in[24];

    int E = in_sizes[1] / 2;
    if (E > EMAX) E = EMAX;

    float *feat, *h1, *mean, *h2;
    uint32_t* wtf;
    cudaGetSymbolAddress((void**)&feat, g_feat);
    cudaGetSymbolAddress((void**)&h1, g_h1);
    cudaGetSymbolAddress((void**)&mean, g_mean);
    cudaGetSymbolAddress((void**)&h2, g_h2);
    cudaGetSymbolAddress((void**)&wtf, g_wtf);

    float* outp = (float*)d_out;            // [N, 2]
    float* em   = (float*)d_out + 2 * NN;   // [N, 160], stride 160

    // weight preconversion
    WC wa;
    wa.src[0] = W_des; wa.src[1] = W_tw; wa.src[2] = W_txt;
    wa.src[3] = W_in;  wa.src[4] = W_l;  wa.src[5] = W_r; wa.src[6] = W_o1;
    int dense[7] = {24576, 24576, 24576, 25600, 25600, 25600, 25600};
    const int PJSZ = 768 * 40;   // 30720
    int dofs[7] = {0, PJSZ, 2 * PJSZ, 3 * PJSZ, 3 * PJSZ + HDSZ32,
                   3 * PJSZ + 2 * HDSZ32, 3 * PJSZ + 3 * HDSZ32};
    for (int s = 0; s < 7; s++) wa.doff[s] = dofs[s];
    wa.cum[0] = 0;
    for (int s = 0; s < 7; s++) wa.cum[s + 1] = wa.cum[s] + dense[s];
    const uint32_t* tWp_des = wtf + dofs[0];
    const uint32_t* tWp_tw  = wtf + dofs[1];
    const uint32_t* tWp_txt = wtf + dofs[2];
    const uint32_t* tW_in   = wtf + dofs[3];
    const uint32_t* tW_l    = wtf + dofs[4];
    const uint32_t* tW_r    = wtf + dofs[5];
    const uint32_t* tW_o1   = wtf + dofs[6];

    // one-time setup (runs on the uncaptured correctness call; reused in capture)
    static cudaStream_t s2 = nullptr;
    static cudaEvent_t evA = nullptr, evB = nullptr, evF = nullptr;
    if (!s2) {
        cudaStreamCreateWithFlags(&s2, cudaStreamNonBlocking);
        cudaEventCreateWithFlags(&evA, cudaEventDisableTiming);
        cudaEventCreateWithFlags(&evB, cudaEventDisableTiming);
        cudaEventCreateWithFlags(&evF, cudaEventDisableTiming);
        cudaFuncSetAttribute((const void*)fw_gemm_p<true, true>,
                             cudaFuncAttributeMaxDynamicSharedMemorySize, FW_SMEM);
        cudaFuncSetAttribute((const void*)fw_pair,
                             cudaFuncAttributeMaxDynamicSharedMemorySize, FW_SMEM);
        cudaFuncSetAttribute((const void*)fw_gemm_out,
                             cudaFuncAttributeMaxDynamicSharedMemorySize, FWO_SMEM);
        cudaFuncSetAttribute((const void*)proj_kernel,
                             cudaFuncAttributeMaxDynamicSharedMemorySize, PJ_SMEM);
    }

    dim3 gProj((NN + 127) / 128, 1, 3);
    int gP = 148;
    int gNode8 = (NN + 7) / 8;
    int gEdge = (E + 255) / 256;

    wconv_kernel<<<(wa.cum[7] + 255) / 256, 256>>>(wa);

    // fork: feat_small + CSR build on s2, overlapping proj below
    cudaEventRecord(evA, 0);
    cudaStreamWaitEvent(s2, evA, 0);
    feat_small_kernel<<<gNode8, 256, 0, s2>>>(num_prop, num_cat, W_np, b_np, W_nc, b_nc, feat);
    cudaEventRecord(evF, s2);
    detect_kernel<<<1, 256, 0, s2>>>(ei, E);
    zero_deg_kernel<<<(NN + 255) / 256, 256, 0, s2>>>();
    count_deg_kernel<<<gEdge, 256, 0, s2>>>(ei, E);
    scan_kernel<<<1, 1024, 0, s2>>>();
    fill_csr_kernel<<<gEdge, 256, 0, s2>>>(ei, E);
    cudaEventRecord(evB, s2);

    // proj -> feat cols 64..159 (disjoint from feat_small's cols 0..63)
    ProjArgs pa;
    pa.A[0] = des; pa.W[0] = tWp_des; pa.b[0] = b_des; pa.off[0] = 64;
    pa.A[1] = tw;  pa.W[1] = tWp_tw;  pa.b[1] = b_tw;  pa.off[1] = 96;
    pa.A[2] = x;   pa.W[2] = tWp_txt; pa.b[2] = b_txt; pa.off[2] = 128;
    proj_kernel<<<gProj, 256, PJ_SMEM>>>(pa, feat, NN);

    cudaStreamWaitEvent(0, evF, 0);   // feat cols 0..63 ready
    // h1 = rtf(leaky(feat @ W_in + b_in))
    fw_gemm_p<true, true><<<gP, 512, FW_SMEM>>>(feat, tW_in, b_in, h1, LD, NN);

    // conv1: h2 = rtf( mean_nbr(h1 @ W_l) + (h1 @ W_r + b_l) )
    fw_pair<<<2 * gP, 512, FW_SMEM>>>(h1, tW_l, tW_r, b_l, mean, feat, NN);
    cudaStreamWaitEvent(0, evB, 0);   // CSR ready before aggregation
    agg_add_kernel<<<gNode8, 256>>>(mean, feat, h2);

    // conv2: h1 = rtf( mean_nbr(h2 @ W_l) + (h2 @ W_r + b_l) )
    fw_pair<<<2 * gP, 512, FW_SMEM>>>(h2, tW_l, tW_r, b_l, mean, feat, NN);
    agg_add_kernel<<<gNode8, 256>>>(mean, feat, h1);

    // em = leaky(h1 @ W_o1 + b_o1) with fused 160->2 head -> out
    fw_gemm_out<<<gP, 512, FWO_SMEM>>>(h1, tW_o1, b_o1, em, NN, W_o2, b_o2, outp);
}